// round 7
// baseline (speedup 1.0000x reference)
#include <cuda_runtime.h>

typedef unsigned long long u64;
#define DI __device__ __forceinline__

// Fixed average-trace buffer (length 120) from the reference module
__constant__ float c_avg[120] = {
 0.0256f,0.0823f,0.1157f,0.1315f,0.1366f,0.1369f,0.1347f,0.1308f,0.1259f,0.1205f,
 0.1146f,0.1086f,0.1028f,0.0970f,0.0913f,0.0858f,0.0805f,0.0756f,0.0708f,0.0664f,
 0.0623f,0.0584f,0.0549f,0.0515f,0.0485f,0.0456f,0.0429f,0.0404f,0.0381f,0.0360f,
 0.0340f,0.0321f,0.0304f,0.0287f,0.0272f,0.0258f,0.0245f,0.0233f,0.0222f,0.0211f,
 0.0201f,0.0191f,0.0182f,0.0173f,0.0165f,0.0158f,0.0150f,0.0143f,0.0137f,0.0130f,
 0.0125f,0.0119f,0.0114f,0.0108f,0.0104f,0.0099f,0.0095f,0.0091f,0.0087f,0.0083f,
 0.0080f,0.0077f,0.0074f,0.0071f,0.0068f,0.0065f,0.0062f,0.0060f,0.0058f,0.0055f,
 0.0053f,0.0050f,0.0049f,0.0047f,0.0045f,0.0044f,0.0042f,0.0040f,0.0039f,0.0038f,
 0.0036f,0.0034f,0.0033f,0.0032f,0.0031f,0.0030f,0.0029f,0.0028f,0.0027f,0.0026f,
 0.0025f,0.0024f,0.0023f,0.0022f,0.0021f,0.0021f,0.0020f,0.0019f,0.0018f,0.0018f,
 0.0017f,0.0017f,0.0016f,0.0016f,0.0015f,0.0015f,0.0014f,0.0014f,0.0013f,0.0013f,
 0.0013f,0.0012f,0.0012f,0.0011f,0.0011f,0.0011f,0.0010f,0.0010f,0.0010f,0.0009f
};

DI u64 pk2(float lo, float hi){ u64 r; asm("mov.b64 %0, {%1,%2};" : "=l"(r) : "f"(lo), "f"(hi)); return r; }
DI void up2(u64 v, float& lo, float& hi){ asm("mov.b64 {%0,%1}, %2;" : "=f"(lo), "=f"(hi) : "l"(v)); }
DI u64 ffma2(u64 a, u64 b, u64 c){ u64 d; asm("fma.rn.f32x2 %0, %1, %2, %3;" : "=l"(d) : "l"(a), "l"(b), "l"(c)); return d; }
DI float hadd2(u64 v){ float lo, hi; up2(v, lo, hi); return lo + hi; }
// Single-MUFU tanh (sm_75+). sigmoid comes pre-halved: sig = 0.5 + 0.5*tanh(x/2),
// with the /2 folded into the staged weights.
DI float tanhfast(float x){ float y; asm("tanh.approx.f32 %0, %1;" : "=f"(y) : "f"(x)); return y; }
DI float sig_h(float xh){ return fmaf(tanhfast(xh), 0.5f, 0.5f); }  // xh = x/2

// Shared memory layout (bytes). 64 sequences per block, 2 threads/seq.
// Row index r = half*15 + j  ->  unit u = 2*j + half.
// i/f/o-gate rows are PRE-SCALED by 0.5 (sigmoid-arg folding); g-gate unscaled.
#define OFF_WIF  0        // ulonglong2 wIF[30][15] : 7200  ({i,f} pairs along k, x0.5)
#define OFF_WGO  7200     // ulonglong2 wGO[30][15] : 7200  ({g,o} pairs: g x1, o x0.5)
#define OFF_BASE 14400    // float4 baseS[15][128]  : 30720 (per-thread 4-gate base; i,f,o x0.5)
#define OFF_W13  45120    // float4 w13S[15][2]     : 480   (trace weights; i,f,o x0.5)
#define OFF_W2   45600    // u64 w2S[4][15]         : 480   (layer-2 weights; i,f,o rows x0.5)
#define SMEM_BYTES 46080

__global__ __launch_bounds__(128, 4)
void lstm_trace_kernel(const float* __restrict__ features,
                       const float* __restrict__ w_ih1,
                       const float* __restrict__ w_hh1,
                       const float* __restrict__ b1,
                       const float* __restrict__ w_ih2,
                       const float* __restrict__ w_hh2,
                       const float* __restrict__ b2,
                       float* __restrict__ out)
{
    extern __shared__ char smraw[];
    ulonglong2* wIF   = (ulonglong2*)(smraw + OFF_WIF);
    ulonglong2* wGO   = (ulonglong2*)(smraw + OFF_WGO);
    float4*     baseS = (float4*)    (smraw + OFF_BASE);
    float4*     w13S  = (float4*)    (smraw + OFF_W13);
    u64*        w2S   = (u64*)       (smraw + OFF_W2);

    const int tid  = threadIdx.x;
    const int half = tid & 1;                    // 0: even units, 1: odd units
    const int seq  = blockIdx.x * 64 + (tid >> 1);

    // ---- stage recurrent weight tables (k-packed pairs, sigmoid gates x0.5) ----
    for (int e = tid; e < 450; e += 128){
        int r  = e / 15, k2 = e % 15;
        int u  = (r < 15) ? 2*r : 2*(r-15) + 1;
        int c0 = 2*k2, c1 = 2*k2 + 1;
        ulonglong2 a, b;
        a.x = pk2(0.5f*w_hh1[      u *30 + c0], 0.5f*w_hh1[      u *30 + c1]);  // i
        a.y = pk2(0.5f*w_hh1[(30 + u)*30 + c0], 0.5f*w_hh1[(30 + u)*30 + c1]);  // f
        b.x = pk2(      w_hh1[(60 + u)*30 + c0],      w_hh1[(60 + u)*30 + c1]); // g
        b.y = pk2(0.5f*w_hh1[(90 + u)*30 + c0], 0.5f*w_hh1[(90 + u)*30 + c1]);  // o
        wIF[e] = a; wGO[e] = b;
    }
    if (tid < 30){
        int j = tid >> 1, hh = tid & 1, u = 2*j + hh;
        float4 v;
        v.x = 0.5f*w_ih1[      u *13 + 12];
        v.y = 0.5f*w_ih1[(30 + u)*13 + 12];
        v.z =       w_ih1[(60 + u)*13 + 12];
        v.w = 0.5f*w_ih1[(90 + u)*13 + 12];
        w13S[j*2 + hh] = v;
    }
    if (tid < 60){
        int g = tid / 15, k2 = tid % 15;
        float s = (g == 2) ? 1.0f : 0.5f;
        w2S[tid] = pk2(s*w_ih2[g*30 + 2*k2], s*w_ih2[g*30 + 2*k2 + 1]);
    }

    // ---- per-thread time-invariant base: b1 + W_x * feat (own 15 units x 4 gates) ----
    {
        float f[12];
        const float4* fp = reinterpret_cast<const float4*>(features) + (size_t)seq * 3;
        float4 fa = fp[0], fb = fp[1], fc = fp[2];
        f[0]=fa.x; f[1]=fa.y; f[2]=fa.z; f[3]=fa.w;
        f[4]=fb.x; f[5]=fb.y; f[6]=fb.z; f[7]=fb.w;
        f[8]=fc.x; f[9]=fc.y; f[10]=fc.z; f[11]=fc.w;
        #pragma unroll
        for (int j = 0; j < 15; j++){
            int u = 2*j + half;
            float4 bs;
            float* bsv = &bs.x;
            #pragma unroll
            for (int g = 0; g < 4; g++){
                int row = g*30 + u;
                float s = __ldg(&b1[row]);
                #pragma unroll
                for (int ff = 0; ff < 12; ff++)
                    s = fmaf(__ldg(&w_ih1[row*13 + ff]), f[ff], s);
                bsv[g] = (g == 2) ? s : 0.5f*s;
            }
            baseS[j*128 + tid] = bs;
        }
    }
    __syncthreads();

    // ---- per-thread recurrent state ----
    u64   hpk[15];                // (h[2j], h[2j+1]) — full layer-1 h, both threads
    float c1v[15];                // cell state for OWN 15 units
    #pragma unroll
    for (int j = 0; j < 15; j++){ hpk[j] = 0ull; c1v[j] = 0.0f; }
    float h2 = 0.0f, c2 = 0.0f;
    const float b2r0 = 0.5f*b2[0], b2r1 = 0.5f*b2[1], b2r2 = b2[2], b2r3 = 0.5f*b2[3];
    const float wh20 = 0.5f*w_hh2[0], wh21 = 0.5f*w_hh2[1], wh22 = w_hh2[2], wh23 = 0.5f*w_hh2[3];
    float* outp = out + (size_t)seq * 120;

    const ulonglong2* myWIF  = wIF + (half*15) * 15;
    const ulonglong2* myWGO  = wGO + (half*15) * 15;
    const float4*     myBase = baseS + tid;      // [j*128]
    const float4*     myW13  = w13S + half;      // [j*2]

    // ---- time recurrence ----
    #pragma unroll 1
    for (int t = 0; t < 120; t++){
        const float av = c_avg[t];
        float newh[15];

        #pragma unroll 5
        for (int j = 0; j < 15; j++){
            const ulonglong2* wif = myWIF + j*15;
            const ulonglong2* wgo = myWGO + j*15;
            float4 bs  = myBase[j*128];
            float4 w13 = myW13[j*2];
            // init packed accumulators with (base, w13*av) so the horizontal add
            // folds both constant terms in for free
            u64 ai = pk2(bs.x, w13.x*av);
            u64 af = pk2(bs.y, w13.y*av);
            u64 ag = pk2(bs.z, w13.z*av);
            u64 ao = pk2(bs.w, w13.w*av);
            #pragma unroll
            for (int k2 = 0; k2 < 15; k2++){
                ulonglong2 a = wif[k2], b = wgo[k2];
                ai = ffma2(a.x, hpk[k2], ai); af = ffma2(a.y, hpk[k2], af);
                ag = ffma2(b.x, hpk[k2], ag); ao = ffma2(b.y, hpk[k2], ao);
            }
            float si = sig_h(hadd2(ai));       // args pre-halved via weight scaling
            float sf = sig_h(hadd2(af));
            float tg = tanhfast(hadd2(ag));
            float so = sig_h(hadd2(ao));

            float cc = fmaf(sf, c1v[j], si*tg);
            c1v[j]  = cc;
            newh[j] = so * tanhfast(cc);
        }

        // exchange new h with partner thread, repack as (even, odd) pairs
        #pragma unroll
        for (int j = 0; j < 15; j++){
            float other = __shfl_xor_sync(0xFFFFFFFFu, newh[j], 1);
            float ev = half ? other   : newh[j];
            float od = half ? newh[j] : other;
            hpk[j] = pk2(ev, od);
        }

        // layer 2 (computed redundantly by both threads of the pair)
        u64 a0 = pk2(b2r0, wh20*h2);
        u64 a1 = pk2(b2r1, wh21*h2);
        u64 a2 = pk2(b2r2, wh22*h2);
        u64 a3 = pk2(b2r3, wh23*h2);
        #pragma unroll
        for (int k2 = 0; k2 < 15; k2++){
            a0 = ffma2(w2S[k2],      hpk[k2], a0);
            a1 = ffma2(w2S[15 + k2], hpk[k2], a1);
            a2 = ffma2(w2S[30 + k2], hpk[k2], a2);
            a3 = ffma2(w2S[45 + k2], hpk[k2], a3);
        }
        float si2 = sig_h(hadd2(a0));
        float sf2 = sig_h(hadd2(a1));
        float tg2 = tanhfast(hadd2(a2));
        float so2 = sig_h(hadd2(a3));
        c2 = fmaf(sf2, c2, si2*tg2);
        h2 = so2 * tanhfast(c2);

        if (!half) outp[t] = h2;
    }
}

extern "C" void kernel_launch(void* const* d_in, const int* in_sizes, int n_in,
                              void* d_out, int out_size)
{
    const float* features = (const float*)d_in[0];
    const float* w_ih1    = (const float*)d_in[1];
    const float* w_hh1    = (const float*)d_in[2];
    const float* b1       = (const float*)d_in[3];
    const float* w_ih2    = (const float*)d_in[4];
    const float* w_hh2    = (const float*)d_in[5];
    const float* b2       = (const float*)d_in[6];
    float* out = (float*)d_out;

    cudaFuncSetAttribute(lstm_trace_kernel,
                         cudaFuncAttributeMaxDynamicSharedMemorySize, SMEM_BYTES);
    lstm_trace_kernel<<<512, 128, SMEM_BYTES>>>(features, w_ih1, w_hh1, b1,
                                                w_ih2, w_hh2, b2, out);
}